// round 15
// baseline (speedup 1.0000x reference)
#include <cuda_runtime.h>
#include <cuda_fp16.h>
#include <math.h>
#include <stdint.h>

#define B_ 4
#define T_ 2048
#define D_ 1024
#define E_ 8
#define F_ 4096
#define N_ (B_*T_)            // 8192 tokens

// ---- gemm1: CTA 128x128, 8 warps (4m x 2n of 32x64), 2 CTAs/SM ----
#define BM1 128
#define BN1 128
#define BK1 64
#define STAGES1 3
#define NT1 256
#define OFF_B1 16384
#define STG1_BYTES 32768
#define SMEM1 (STAGES1*STG1_BYTES)      // 98304/CTA

// ---- gemm2: CTA 128x256, 16 warps (4m x 4n of 32x64), 1 CTA/SM, split-K=2 ----
#define BM2 128
#define BN2 256
#define BK2 128
#define NT2 512
#define OFF_B2 32768
#define STG2_BYTES 98304
#define SMEM2 (2*STG2_BYTES)            // 196608

// ---------------- device scratch ---------------------------------------------
__device__ int    g_cnt[E_];
__device__ int    g_tok[E_*N_];
__device__ float  g_gate[E_*N_];
__device__ __half g_x_h[(size_t)N_*D_];
__device__ __half g_w1t[(size_t)E_*F_*D_];   // [E][F][D] K-major
__device__ __half g_w2t[(size_t)E_*D_*F_];   // [E][D][F] K-major
__device__ __half g_h[(size_t)N_*2*F_];      // [N*K][F]

// ---------------- helpers -----------------------------------------------------
__device__ __forceinline__ uint32_t smem_u32(const void* p) {
    uint32_t a;
    asm("{ .reg .u64 t; cvta.to.shared.u64 t, %1; cvt.u32.u64 %0, t; }"
        : "=r"(a) : "l"(p));
    return a;
}
__device__ __forceinline__ void cp16(uint32_t dst, const void* src) {
    asm volatile("cp.async.cg.shared.global [%0], [%1], 16;"
                 :: "r"(dst), "l"(src) : "memory");
}
__device__ __forceinline__ void cp_commit() {
    asm volatile("cp.async.commit_group;" ::: "memory");
}
template<int NN>
__device__ __forceinline__ void cp_wait() {
    asm volatile("cp.async.wait_group %0;" :: "n"(NN) : "memory");
}
__device__ __forceinline__ void ldm4(uint32_t& r0, uint32_t& r1,
                                     uint32_t& r2, uint32_t& r3, uint32_t a) {
    asm volatile("ldmatrix.sync.aligned.m8n8.x4.shared.b16 {%0,%1,%2,%3}, [%4];"
                 : "=r"(r0), "=r"(r1), "=r"(r2), "=r"(r3) : "r"(a));
}
__device__ __forceinline__ void mma16816(float* c, const uint32_t* a,
                                         uint32_t b0, uint32_t b1) {
    asm volatile(
        "mma.sync.aligned.m16n8k16.row.col.f32.f16.f16.f32 "
        "{%0,%1,%2,%3}, {%4,%5,%6,%7}, {%8,%9}, {%0,%1,%2,%3};"
        : "+f"(c[0]), "+f"(c[1]), "+f"(c[2]), "+f"(c[3])
        : "r"(a[0]), "r"(a[1]), "r"(a[2]), "r"(a[3]), "r"(b0), "r"(b1));
}
__device__ __forceinline__ uint32_t pack2(__half a, __half b) {
    return (uint32_t)__half_as_ushort(a) | ((uint32_t)__half_as_ushort(b) << 16);
}
__device__ __forceinline__ float gelu_f(float v) {
    return 0.5f * v * (1.f + erff(v * 0.70710678118654752440f));
}

// ------- fused pre kernel: w1-prep, gate+x->fp16, w2-prep in ONE launch -------
#define W1PBLKS  ((F_/32)*(D_/64)*E_)            // 16384
#define GATEBLKS (N_/8)                          // 1024
#define W2PBLKS  ((D_/32)*(F_/64)*E_)            // 16384

__global__ void pre_kernel(const float* __restrict__ x,
                           const float* __restrict__ gw,
                           const float* __restrict__ w1,
                           const float* __restrict__ w2) {
    __shared__ float tile[64][33];      // prep scratch (8.4 KB)
    __shared__ float sgw[E_][D_];       // gate weights (32 KB)
    int bb  = blockIdx.x;
    int tid = threadIdx.x;

    if (bb < W1PBLKS || bb >= W1PBLKS + GATEBLKS) {
        // ---- weight transpose+convert: one 32col x 64row subtile per block ----
        const float* w; __half* wt;
        int RIN, CIN, bid;
        if (bb < W1PBLKS) {
            bid = bb; w = w1; wt = g_w1t; RIN = D_; CIN = F_;
        } else {
            bid = bb - W1PBLKS - GATEBLKS; w = w2; wt = g_w2t; RIN = F_; CIN = D_;
        }
        int tx = tid & 31, ty = tid >> 5;          // (32, 8)
        int cb = CIN / 32, rb = RIN / 64;
        int e   = bid / (cb * rb);
        int rem = bid % (cb * rb);
        int c0  = (rem % cb) * 32, r0 = (rem / cb) * 64;
        const float* wi = w + (size_t)e * RIN * CIN;
        #pragma unroll
        for (int i = 0; i < 8; i++)
            tile[ty + 8*i][tx] = wi[(size_t)(r0 + ty + 8*i) * CIN + c0 + tx];
        __syncthreads();
        size_t ob = (size_t)e * CIN * RIN;
        #pragma unroll
        for (int j = 0; j < 4; j++) {
            int c = ty * 4 + j;
            uint32_t v = pack2(__float2half_rn(tile[2*tx][c]),
                               __float2half_rn(tile[2*tx + 1][c]));
            *(uint32_t*)(wt + ob + (size_t)(c0 + c) * RIN + r0 + 2*tx) = v;
        }
        return;
    }

    // ---- gate + x conversion: 8 tokens per block, warp per token ----
    for (int idx = tid; idx < D_ * E_; idx += 256) {
        int d = idx >> 3, e = idx & 7;
        sgw[e][d] = gw[idx];
    }
    __syncthreads();

    int wid = tid >> 5, lane = tid & 31;
    int t = (bb - W1PBLKS) * 8 + wid;
    const float* xr = x + (size_t)t * D_;
    uint2* xh = (uint2*)(g_x_h + (size_t)t * D_);
    float acc[E_];
    #pragma unroll
    for (int e = 0; e < E_; e++) acc[e] = 0.f;
    #pragma unroll
    for (int i = 0; i < 8; i++) {
        int d0 = i * 128 + lane * 4;
        float4 v = *(const float4*)(xr + d0);
        xh[d0 >> 2] = make_uint2(
            pack2(__float2half_rn(v.x), __float2half_rn(v.y)),
            pack2(__float2half_rn(v.z), __float2half_rn(v.w)));
        #pragma unroll
        for (int e = 0; e < E_; e++) {
            float4 g = *(const float4*)&sgw[e][d0];   // LDS.128, conflict-free
            acc[e] += v.x * g.x + v.y * g.y + v.z * g.z + v.w * g.w;
        }
    }
    #pragma unroll
    for (int e = 0; e < E_; e++)
        #pragma unroll
        for (int o = 16; o > 0; o >>= 1)
            acc[e] += __shfl_xor_sync(0xffffffffu, acc[e], o);
    if (lane == 0) {
        int i0 = 0; float v0 = acc[0];
        #pragma unroll
        for (int e = 1; e < E_; e++) if (acc[e] > v0) { v0 = acc[e]; i0 = e; }
        int i1 = -1; float v1 = -1e30f;
        #pragma unroll
        for (int e = 0; e < E_; e++) if (e != i0 && acc[e] > v1) { v1 = acc[e]; i1 = e; }
        float e1 = expf(v1 - v0), inv = 1.f / (1.f + e1);
        int p0 = atomicAdd(&g_cnt[i0], 1);
        g_tok[i0 * N_ + p0] = t;  g_gate[i0 * N_ + p0] = inv;
        int p1 = atomicAdd(&g_cnt[i1], 1);
        g_tok[i1 * N_ + p1] = t;  g_gate[i1 * N_ + p1] = e1 * inv;
    }
}

// ---------------- gemm1: h = gelu(gather(x) @ w1t^T + b1) ---------------------
__global__ __launch_bounds__(NT1, 2)
void gemm1_kernel(const float* __restrict__ b1) {
    int e   = blockIdx.z;
    int cnt = g_cnt[e];
    int m0  = blockIdx.y * BM1;
    if (m0 >= cnt) return;
    int n0  = blockIdx.x * BN1;
    int off = 0;
    #pragma unroll
    for (int j = 0; j < E_; j++) if (j < e) off += g_cnt[j];

    extern __shared__ __align__(1024) char smem[];
    uint32_t sb = smem_u32(smem);
    int tid = threadIdx.x, wid = tid >> 5, lane = tid & 31;

    const __half* Bp = g_w1t + (size_t)e * (size_t)F_ * D_;

    int rbase = tid >> 3;
    int ch    = tid & 7;
    int csw   = ch ^ (rbase & 7);
    uint32_t dst = (uint32_t)(rbase * 128 + csw * 16);

    const __half* a_p[4];
    #pragma unroll
    for (int i = 0; i < 4; i++) {
        int grow = min(m0 + rbase + 32 * i, cnt - 1);
        a_p[i] = g_x_h + (size_t)g_tok[e * N_ + grow] * D_ + ch * 8;
    }
    const __half* b_p = Bp + (size_t)(n0 + rbase) * D_ + ch * 8;

    auto load_stage = [&](int kt, int slot) {
        uint32_t s0 = sb + slot * STG1_BYTES;
        int koff = kt * BK1;
        #pragma unroll
        for (int i = 0; i < 4; i++)
            cp16(s0 + dst + i * 4096u, a_p[i] + koff);
        #pragma unroll
        for (int i = 0; i < 4; i++)
            cp16(s0 + OFF_B1 + dst + i * 4096u, b_p + koff + i * (32 * D_));
    };

    int m_warp = (wid & 3) * 32;
    int n_warp = (wid >> 2) * 64;
    uint32_t a_rowb[2], b_rowb[4];
    #pragma unroll
    for (int mf = 0; mf < 2; mf++)
        a_rowb[mf] = (uint32_t)((m_warp + mf * 16 + (lane & 15)) * 128);
    #pragma unroll
    for (int q = 0; q < 4; q++)
        b_rowb[q] = (uint32_t)((n_warp + q * 16 + ((lane & 16) >> 1) + (lane & 7)) * 128);
    uint32_t a_chsel = (uint32_t)(lane >> 4);
    uint32_t b_chsel = (uint32_t)((lane >> 3) & 1);
    uint32_t lxor    = (uint32_t)(lane & 7);

    float acc[2][8][4];
    #pragma unroll
    for (int mf = 0; mf < 2; mf++)
        #pragma unroll
        for (int nb = 0; nb < 8; nb++)
            #pragma unroll
            for (int i = 0; i < 4; i++) acc[mf][nb][i] = 0.f;

    constexpr int KTT = D_ / BK1;    // 16
    load_stage(0, 0); cp_commit();
    load_stage(1, 1); cp_commit();

    for (int kt = 0; kt < KTT; kt++) {
        cp_wait<1>();
        __syncthreads();
        // issue next prefetch BEFORE compute (buffer (kt+2)%3 was last read
        // by compute(kt-1); the barrier above orders all warps past it)
        if (kt + 2 < KTT) {
            load_stage(kt + 2, (kt + 2) % STAGES1);
            cp_commit();
        }

        uint32_t s0 = sb + (kt % STAGES1) * STG1_BYTES;
        #pragma unroll
        for (int ks = 0; ks < 4; ks++) {
            uint32_t ach = (((2 * (uint32_t)ks + a_chsel) ^ lxor) << 4);
            uint32_t bch = (((2 * (uint32_t)ks + b_chsel) ^ lxor) << 4);
            uint32_t af[2][4], bf[4][4];
            #pragma unroll
            for (int mf = 0; mf < 2; mf++)
                ldm4(af[mf][0], af[mf][1], af[mf][2], af[mf][3],
                     s0 + a_rowb[mf] + ach);
            #pragma unroll
            for (int q = 0; q < 4; q++)
                ldm4(bf[q][0], bf[q][1], bf[q][2], bf[q][3],
                     s0 + OFF_B1 + b_rowb[q] + bch);
            #pragma unroll
            for (int q = 0; q < 4; q++) {
                #pragma unroll
                for (int mf = 0; mf < 2; mf++) {
                    mma16816(acc[mf][2*q],   af[mf], bf[q][0], bf[q][1]);
                    mma16816(acc[mf][2*q+1], af[mf], bf[q][2], bf[q][3]);
                }
            }
        }
        if (kt + 2 >= KTT) cp_commit();   // keep group count consistent
    }

    const float* bias = b1 + (size_t)e * F_ + n0;
    #pragma unroll
    for (int mf = 0; mf < 2; mf++) {
        #pragma unroll
        for (int hh = 0; hh < 2; hh++) {
            int lr = m_warp + mf * 16 + hh * 8 + (lane >> 2);
            int r  = m0 + lr;
            if (r >= cnt) continue;
            __half* ph = g_h + (size_t)(off + r) * F_ + n0;
            #pragma unroll
            for (int nb = 0; nb < 8; nb++) {
                int col = n_warp + nb * 8 + 2 * (lane & 3);
                float2 bv = *(const float2*)(bias + col);
                float v0 = gelu_f(acc[mf][nb][hh*2]     + bv.x);
                float v1 = gelu_f(acc[mf][nb][hh*2 + 1] + bv.y);
                *(uint32_t*)(ph + col) =
                    pack2(__float2half_rn(v0), __float2half_rn(v1));
            }
        }
    }
}

// ---------------- gemm2: out += gate * (h @ w2t^T + b2), split-K=2 ------------
__global__ __launch_bounds__(NT2, 1)
void gemm2_kernel(const float* __restrict__ b2, float* __restrict__ out) {
    constexpr int KT  = F_;
    constexpr int KTT = (F_/2) / BK2;       // 16

    int z = blockIdx.z;
    int e = z >> 1, split = z & 1;
    int kbase = split * (F_/2);

    int cnt = g_cnt[e];
    int m0  = blockIdx.y * BM2;
    if (m0 >= cnt) return;
    int n0  = blockIdx.x * BN2;
    int off = 0;
    #pragma unroll
    for (int j = 0; j < E_; j++) if (j < e) off += g_cnt[j];

    extern __shared__ __align__(1024) char smem[];
    uint32_t sb = smem_u32(smem);
    int tid = threadIdx.x, wid = tid >> 5, lane = tid & 31;

    const __half* Bp = g_w2t + (size_t)e * (size_t)D_ * KT;

    int rbase = tid >> 4;              // 0..31
    int ch    = tid & 15;
    int csw   = ch ^ (rbase & 7);
    uint32_t dst = (uint32_t)(rbase * 256 + csw * 16);

    const __half* a_p[4];
    #pragma unroll
    for (int i = 0; i < 4; i++) {
        int grow = min(m0 + rbase + 32 * i, cnt - 1);
        a_p[i] = g_h + (size_t)(off + grow) * KT + ch * 8 + kbase;
    }
    const __half* b_p = Bp + (size_t)(n0 + rbase) * KT + ch * 8 + kbase;

    auto load_stage = [&](int kt, int slot) {
        uint32_t s0 = sb + slot * STG2_BYTES;
        int koff = kt * BK2;
        #pragma unroll
        for (int i = 0; i < 4; i++)
            cp16(s0 + dst + i * 8192u, a_p[i] + koff);
        #pragma unroll
        for (int i = 0; i < 8; i++)
            cp16(s0 + OFF_B2 + dst + i * 8192u, b_p + koff + i * (32 * KT));
    };

    int m_warp = (wid & 3) * 32;
    int n_warp = (wid >> 2) * 64;
    uint32_t a_rowb[2], b_rowb[4];
    #pragma unroll
    for (int mf = 0; mf < 2; mf++)
        a_rowb[mf] = (uint32_t)((m_warp + mf * 16 + (lane & 15)) * 256);
    #pragma unroll
    for (int q = 0; q < 4; q++)
        b_rowb[q] = (uint32_t)((n_warp + q * 16 + ((lane & 16) >> 1) + (lane & 7)) * 256);
    uint32_t a_chsel = (uint32_t)(lane >> 4);
    uint32_t b_chsel = (uint32_t)((lane >> 3) & 1);
    uint32_t lxor    = (uint32_t)(lane & 7);

    float acc[2][8][4];
    #pragma unroll
    for (int mf = 0; mf < 2; mf++)
        #pragma unroll
        for (int nb = 0; nb < 8; nb++)
            #pragma unroll
            for (int i = 0; i < 4; i++) acc[mf][nb][i] = 0.f;

    load_stage(0, 0);
    cp_commit();

    for (int kt = 0; kt < KTT; kt++) {
        cp_wait<0>();
        __syncthreads();
        if (kt + 1 < KTT) {
            load_stage(kt + 1, (kt + 1) & 1);
            cp_commit();
        }

        uint32_t s0 = sb + (kt & 1) * STG2_BYTES;
        #pragma unroll
        for (int ks = 0; ks < 8; ks++) {
            uint32_t ach = (((2 * (uint32_t)ks + a_chsel) ^ lxor) << 4);
            uint32_t bch = (((2 * (uint32_t)ks + b_chsel) ^ lxor) << 4);
            uint32_t af[2][4], bf[4][4];
            #pragma unroll
            for (int mf = 0; mf < 2; mf++)
                ldm4(af[mf][0], af[mf][1], af[mf][2], af[mf][3],
                     s0 + a_rowb[mf] + ach);
            #pragma unroll
            for (int q = 0; q < 4; q++)
                ldm4(bf[q][0], bf[q][1], bf[q][2], bf[q][3],
                     s0 + OFF_B2 + b_rowb[q] + bch);
            #pragma unroll
            for (int q = 0; q < 4; q++) {
                #pragma unroll
                for (int mf = 0; mf < 2; mf++) {
                    mma16816(acc[mf][2*q],   af[mf], bf[q][0], bf[q][1]);
                    mma16816(acc[mf][2*q+1], af[mf], bf[q][2], bf[q][3]);
                }
            }
        }
    }

    const float* bias = b2 + (size_t)e * D_ + n0;
    #pragma unroll
    for (int mf = 0; mf < 2; mf++) {
        #pragma unroll
        for (int hh = 0; hh < 2; hh++) {
            int lr = m_warp + mf * 16 + hh * 8 + (lane >> 2);
            int r  = m0 + lr;
            if (r >= cnt) continue;
            int   tok = g_tok[e * N_ + r];
            float gv  = g_gate[e * N_ + r];
            float* orow = out + (size_t)tok * D_ + n0;
            #pragma unroll
            for (int nb = 0; nb < 8; nb++) {
                int col = n_warp + nb * 8 + 2 * (lane & 3);
                float bx = 0.f, by = 0.f;
                if (split == 0) {
                    float2 bv = *(const float2*)(bias + col);
                    bx = bv.x; by = bv.y;
                }
                atomicAdd(orow + col,     gv * (acc[mf][nb][hh*2]     + bx));
                atomicAdd(orow + col + 1, gv * (acc[mf][nb][hh*2 + 1] + by));
            }
        }
    }
}

// ---------------- launch --------------------------------------------------------
extern "C" void kernel_launch(void* const* d_in, const int* in_sizes, int n_in,
                              void* d_out, int out_size) {
    const float* x  = (const float*)d_in[0];
    const float* gw = (const float*)d_in[1];
    const float* w1 = (const float*)d_in[2];
    const float* b1 = (const float*)d_in[3];
    const float* w2 = (const float*)d_in[4];
    const float* b2 = (const float*)d_in[5];
    float* out = (float*)d_out;

    static void* cnt_ptr = nullptr;
    if (cnt_ptr == nullptr) {
        cudaGetSymbolAddress(&cnt_ptr, g_cnt);
        cudaFuncSetAttribute(gemm1_kernel,
                             cudaFuncAttributeMaxDynamicSharedMemorySize, SMEM1);
        cudaFuncSetAttribute(gemm2_kernel,
                             cudaFuncAttributeMaxDynamicSharedMemorySize, SMEM2);
    }

    cudaMemsetAsync(out, 0, (size_t)out_size * sizeof(float), 0);
    cudaMemsetAsync(cnt_ptr, 0, E_ * sizeof(int), 0);
    pre_kernel<<<W1PBLKS + GATEBLKS + W2PBLKS, 256>>>(x, gw, w1, w2);

    dim3 g1(F_/BN1, N_/BM1, E_);         // (32, 64, 8), cnt-guarded
    gemm1_kernel<<<g1, NT1, SMEM1>>>(b1);

    dim3 g2(D_/BN2, N_/BM2, E_ * 2);     // (4, 64, 16): split-K=2, cnt-guarded
    gemm2_kernel<<<g2, NT2, SMEM2>>>(b2, out);
}

// round 16
// speedup vs baseline: 1.0242x; 1.0242x over previous
#include <cuda_runtime.h>
#include <cuda_fp16.h>
#include <math.h>
#include <stdint.h>

#define B_ 4
#define T_ 2048
#define D_ 1024
#define E_ 8
#define F_ 4096
#define N_ (B_*T_)            // 8192 tokens

// ---- gemm1: CTA 128x128, 8 warps (4m x 2n of 32x64), 2 CTAs/SM ----
#define BM1 128
#define BN1 128
#define BK1 64
#define STAGES1 3
#define NT1 256
#define OFF_B1 16384
#define STG1_BYTES 32768
#define SMEM1 (STAGES1*STG1_BYTES)      // 98304/CTA

// ---- gemm2: CTA 128x256, 16 warps (4m x 4n of 32x64), 1 CTA/SM, split-K=2 ----
#define BM2 128
#define BN2 256
#define BK2 128
#define NT2 512
#define OFF_B2 32768
#define STG2_BYTES 98304
#define SMEM2 (2*STG2_BYTES)            // 196608

// ---------------- device scratch ---------------------------------------------
__device__ int    g_cnt[E_];
__device__ int    g_tok[E_*N_];
__device__ float  g_gate[E_*N_];
__device__ __half g_x_h[(size_t)N_*D_];
__device__ __half g_w1t[(size_t)E_*F_*D_];   // [E][F][D] K-major
__device__ __half g_w2t[(size_t)E_*D_*F_];   // [E][D][F] K-major
__device__ __half g_h[(size_t)N_*2*F_];      // [N*K][F]

// ---------------- helpers -----------------------------------------------------
__device__ __forceinline__ uint32_t smem_u32(const void* p) {
    uint32_t a;
    asm("{ .reg .u64 t; cvta.to.shared.u64 t, %1; cvt.u32.u64 %0, t; }"
        : "=r"(a) : "l"(p));
    return a;
}
__device__ __forceinline__ void cp16(uint32_t dst, const void* src) {
    asm volatile("cp.async.cg.shared.global [%0], [%1], 16;"
                 :: "r"(dst), "l"(src) : "memory");
}
__device__ __forceinline__ void cp_commit() {
    asm volatile("cp.async.commit_group;" ::: "memory");
}
template<int NN>
__device__ __forceinline__ void cp_wait() {
    asm volatile("cp.async.wait_group %0;" :: "n"(NN) : "memory");
}
__device__ __forceinline__ void ldm4(uint32_t& r0, uint32_t& r1,
                                     uint32_t& r2, uint32_t& r3, uint32_t a) {
    asm volatile("ldmatrix.sync.aligned.m8n8.x4.shared.b16 {%0,%1,%2,%3}, [%4];"
                 : "=r"(r0), "=r"(r1), "=r"(r2), "=r"(r3) : "r"(a));
}
__device__ __forceinline__ void mma16816(float* c, const uint32_t* a,
                                         uint32_t b0, uint32_t b1) {
    asm volatile(
        "mma.sync.aligned.m16n8k16.row.col.f32.f16.f16.f32 "
        "{%0,%1,%2,%3}, {%4,%5,%6,%7}, {%8,%9}, {%0,%1,%2,%3};"
        : "+f"(c[0]), "+f"(c[1]), "+f"(c[2]), "+f"(c[3])
        : "r"(a[0]), "r"(a[1]), "r"(a[2]), "r"(a[3]), "r"(b0), "r"(b1));
}
__device__ __forceinline__ uint32_t pack2(__half a, __half b) {
    return (uint32_t)__half_as_ushort(a) | ((uint32_t)__half_as_ushort(b) << 16);
}
__device__ __forceinline__ float gelu_f(float v) {
    return 0.5f * v * (1.f + erff(v * 0.70710678118654752440f));
}

// ------- gate kernel: smem-staged gw + fused x->fp16 conversion ---------------
__global__ void gate_kernel(const float* __restrict__ x,
                            const float* __restrict__ gw) {
    __shared__ float sgw[E_][D_];      // [e][d], 32KB
    int tid = threadIdx.x;
    for (int idx = tid; idx < D_ * E_; idx += 256) {
        int d = idx >> 3, e = idx & 7;
        sgw[e][d] = gw[idx];
    }
    __syncthreads();

    int wid = tid >> 5, lane = tid & 31;
    int t = blockIdx.x * 8 + wid;
    const float* xr = x + (size_t)t * D_;
    uint2* xh = (uint2*)(g_x_h + (size_t)t * D_);
    float acc[E_];
    #pragma unroll
    for (int e = 0; e < E_; e++) acc[e] = 0.f;
    #pragma unroll
    for (int i = 0; i < 8; i++) {
        int d0 = i * 128 + lane * 4;
        float4 v = *(const float4*)(xr + d0);
        xh[d0 >> 2] = make_uint2(
            pack2(__float2half_rn(v.x), __float2half_rn(v.y)),
            pack2(__float2half_rn(v.z), __float2half_rn(v.w)));
        #pragma unroll
        for (int e = 0; e < E_; e++) {
            float4 g = *(const float4*)&sgw[e][d0];   // LDS.128, conflict-free
            acc[e] += v.x * g.x + v.y * g.y + v.z * g.z + v.w * g.w;
        }
    }
    #pragma unroll
    for (int e = 0; e < E_; e++)
        #pragma unroll
        for (int o = 16; o > 0; o >>= 1)
            acc[e] += __shfl_xor_sync(0xffffffffu, acc[e], o);
    if (lane == 0) {
        int i0 = 0; float v0 = acc[0];
        #pragma unroll
        for (int e = 1; e < E_; e++) if (acc[e] > v0) { v0 = acc[e]; i0 = e; }
        int i1 = -1; float v1 = -1e30f;
        #pragma unroll
        for (int e = 0; e < E_; e++) if (e != i0 && acc[e] > v1) { v1 = acc[e]; i1 = e; }
        float e1 = expf(v1 - v0), inv = 1.f / (1.f + e1);
        int p0 = atomicAdd(&g_cnt[i0], 1);
        g_tok[i0 * N_ + p0] = t;  g_gate[i0 * N_ + p0] = inv;
        int p1 = atomicAdd(&g_cnt[i1], 1);
        g_tok[i1 * N_ + p1] = t;  g_gate[i1 * N_ + p1] = e1 * inv;
    }
}

// ------- prep_w: transpose->fp16, 32col x 64row subtile, uint4 stores ---------
#define W1PBLKS ((F_/32)*(D_/64)*E_)            // 16384
#define W2PBLKS ((D_/32)*(F_/64)*E_)            // 16384

__global__ void prep_w_kernel(const float* __restrict__ w1,
                              const float* __restrict__ w2) {
    __shared__ float tile[64][33];
    int bb  = blockIdx.x;
    int tid = threadIdx.x;
    const float* w; __half* wt;
    int RIN, CIN, bid;
    if (bb < W1PBLKS) {
        bid = bb; w = w1; wt = g_w1t; RIN = D_; CIN = F_;
    } else {
        bid = bb - W1PBLKS; w = w2; wt = g_w2t; RIN = F_; CIN = D_;
    }
    int cb = CIN / 32, rb = RIN / 64;
    int e   = bid / (cb * rb);
    int rem = bid % (cb * rb);
    int c0  = (rem % cb) * 32, r0 = (rem / cb) * 64;
    const float* wi = w + (size_t)e * RIN * CIN;
    {   // load: (32, 8) layout, coalesced rows
        int tx = tid & 31, ty = tid >> 5;
        #pragma unroll
        for (int i = 0; i < 8; i++)
            tile[ty + 8*i][tx] = wi[(size_t)(r0 + ty + 8*i) * CIN + c0 + tx];
    }
    __syncthreads();
    // store: thread -> (c = tid>>3, rg = tid&7); pack 8 rows -> one uint4
    {
        int c  = tid >> 3;          // 0..31
        int rg = tid & 7;           // 0..7
        uint32_t p[4];
        #pragma unroll
        for (int k = 0; k < 4; k++)
            p[k] = pack2(__float2half_rn(tile[8*rg + 2*k][c]),
                         __float2half_rn(tile[8*rg + 2*k + 1][c]));
        size_t ob = (size_t)e * CIN * RIN;
        *(uint4*)(wt + ob + (size_t)(c0 + c) * RIN + r0 + 8*rg) =
            make_uint4(p[0], p[1], p[2], p[3]);
    }
}

// ---------------- gemm1: h = gelu(gather(x) @ w1t^T + b1) ---------------------
__global__ __launch_bounds__(NT1, 2)
void gemm1_kernel(const float* __restrict__ b1) {
    int e   = blockIdx.z;
    int cnt = g_cnt[e];
    int m0  = blockIdx.y * BM1;
    if (m0 >= cnt) return;
    int n0  = blockIdx.x * BN1;
    int off = 0;
    #pragma unroll
    for (int j = 0; j < E_; j++) if (j < e) off += g_cnt[j];

    extern __shared__ __align__(1024) char smem[];
    uint32_t sb = smem_u32(smem);
    int tid = threadIdx.x, wid = tid >> 5, lane = tid & 31;

    const __half* Bp = g_w1t + (size_t)e * (size_t)F_ * D_;

    int rbase = tid >> 3;
    int ch    = tid & 7;
    int csw   = ch ^ (rbase & 7);
    uint32_t dst = (uint32_t)(rbase * 128 + csw * 16);

    const __half* a_p[4];
    #pragma unroll
    for (int i = 0; i < 4; i++) {
        int grow = min(m0 + rbase + 32 * i, cnt - 1);
        a_p[i] = g_x_h + (size_t)g_tok[e * N_ + grow] * D_ + ch * 8;
    }
    const __half* b_p = Bp + (size_t)(n0 + rbase) * D_ + ch * 8;

    auto load_stage = [&](int kt, int slot) {
        uint32_t s0 = sb + slot * STG1_BYTES;
        int koff = kt * BK1;
        #pragma unroll
        for (int i = 0; i < 4; i++)
            cp16(s0 + dst + i * 4096u, a_p[i] + koff);
        #pragma unroll
        for (int i = 0; i < 4; i++)
            cp16(s0 + OFF_B1 + dst + i * 4096u, b_p + koff + i * (32 * D_));
    };

    int m_warp = (wid & 3) * 32;
    int n_warp = (wid >> 2) * 64;
    uint32_t a_rowb[2], b_rowb[4];
    #pragma unroll
    for (int mf = 0; mf < 2; mf++)
        a_rowb[mf] = (uint32_t)((m_warp + mf * 16 + (lane & 15)) * 128);
    #pragma unroll
    for (int q = 0; q < 4; q++)
        b_rowb[q] = (uint32_t)((n_warp + q * 16 + ((lane & 16) >> 1) + (lane & 7)) * 128);
    uint32_t a_chsel = (uint32_t)(lane >> 4);
    uint32_t b_chsel = (uint32_t)((lane >> 3) & 1);
    uint32_t lxor    = (uint32_t)(lane & 7);

    float acc[2][8][4];
    #pragma unroll
    for (int mf = 0; mf < 2; mf++)
        #pragma unroll
        for (int nb = 0; nb < 8; nb++)
            #pragma unroll
            for (int i = 0; i < 4; i++) acc[mf][nb][i] = 0.f;

    constexpr int KTT = D_ / BK1;    // 16
    load_stage(0, 0); cp_commit();
    load_stage(1, 1); cp_commit();

    for (int kt = 0; kt < KTT; kt++) {
        cp_wait<1>();
        __syncthreads();

        uint32_t s0 = sb + (kt % STAGES1) * STG1_BYTES;
        #pragma unroll
        for (int ks = 0; ks < 4; ks++) {
            uint32_t ach = (((2 * (uint32_t)ks + a_chsel) ^ lxor) << 4);
            uint32_t bch = (((2 * (uint32_t)ks + b_chsel) ^ lxor) << 4);
            uint32_t af[2][4], bf[4][4];
            #pragma unroll
            for (int mf = 0; mf < 2; mf++)
                ldm4(af[mf][0], af[mf][1], af[mf][2], af[mf][3],
                     s0 + a_rowb[mf] + ach);
            #pragma unroll
            for (int q = 0; q < 4; q++)
                ldm4(bf[q][0], bf[q][1], bf[q][2], bf[q][3],
                     s0 + OFF_B1 + b_rowb[q] + bch);
            #pragma unroll
            for (int q = 0; q < 4; q++) {
                #pragma unroll
                for (int mf = 0; mf < 2; mf++) {
                    mma16816(acc[mf][2*q],   af[mf], bf[q][0], bf[q][1]);
                    mma16816(acc[mf][2*q+1], af[mf], bf[q][2], bf[q][3]);
                }
            }
        }

        if (kt + 2 < KTT) load_stage(kt + 2, (kt + 2) % STAGES1);
        cp_commit();
    }

    const float* bias = b1 + (size_t)e * F_ + n0;
    #pragma unroll
    for (int mf = 0; mf < 2; mf++) {
        #pragma unroll
        for (int hh = 0; hh < 2; hh++) {
            int lr = m_warp + mf * 16 + hh * 8 + (lane >> 2);
            int r  = m0 + lr;
            if (r >= cnt) continue;
            __half* ph = g_h + (size_t)(off + r) * F_ + n0;
            #pragma unroll
            for (int nb = 0; nb < 8; nb++) {
                int col = n_warp + nb * 8 + 2 * (lane & 3);
                float2 bv = *(const float2*)(bias + col);
                float v0 = gelu_f(acc[mf][nb][hh*2]     + bv.x);
                float v1 = gelu_f(acc[mf][nb][hh*2 + 1] + bv.y);
                *(uint32_t*)(ph + col) =
                    pack2(__float2half_rn(v0), __float2half_rn(v1));
            }
        }
    }
}

// ---------------- gemm2: out += gate * (h @ w2t^T + b2), split-K=2 ------------
__global__ __launch_bounds__(NT2, 1)
void gemm2_kernel(const float* __restrict__ b2, float* __restrict__ out) {
    constexpr int KT  = F_;
    constexpr int KTT = (F_/2) / BK2;       // 16

    int z = blockIdx.z;
    int e = z >> 1, split = z & 1;
    int kbase = split * (F_/2);

    int cnt = g_cnt[e];
    int m0  = blockIdx.y * BM2;
    if (m0 >= cnt) return;
    int n0  = blockIdx.x * BN2;
    int off = 0;
    #pragma unroll
    for (int j = 0; j < E_; j++) if (j < e) off += g_cnt[j];

    extern __shared__ __align__(1024) char smem[];
    uint32_t sb = smem_u32(smem);
    int tid = threadIdx.x, wid = tid >> 5, lane = tid & 31;

    const __half* Bp = g_w2t + (size_t)e * (size_t)D_ * KT;

    int rbase = tid >> 4;              // 0..31
    int ch    = tid & 15;
    int csw   = ch ^ (rbase & 7);
    uint32_t dst = (uint32_t)(rbase * 256 + csw * 16);

    const __half* a_p[4];
    #pragma unroll
    for (int i = 0; i < 4; i++) {
        int grow = min(m0 + rbase + 32 * i, cnt - 1);
        a_p[i] = g_h + (size_t)(off + grow) * KT + ch * 8 + kbase;
    }
    const __half* b_p = Bp + (size_t)(n0 + rbase) * KT + ch * 8 + kbase;

    auto load_stage = [&](int kt, int slot) {
        uint32_t s0 = sb + slot * STG2_BYTES;
        int koff = kt * BK2;
        #pragma unroll
        for (int i = 0; i < 4; i++)
            cp16(s0 + dst + i * 8192u, a_p[i] + koff);
        #pragma unroll
        for (int i = 0; i < 8; i++)
            cp16(s0 + OFF_B2 + dst + i * 8192u, b_p + koff + i * (32 * KT));
    };

    int m_warp = (wid & 3) * 32;
    int n_warp = (wid >> 2) * 64;
    uint32_t a_rowb[2], b_rowb[4];
    #pragma unroll
    for (int mf = 0; mf < 2; mf++)
        a_rowb[mf] = (uint32_t)((m_warp + mf * 16 + (lane & 15)) * 256);
    #pragma unroll
    for (int q = 0; q < 4; q++)
        b_rowb[q] = (uint32_t)((n_warp + q * 16 + ((lane & 16) >> 1) + (lane & 7)) * 256);
    uint32_t a_chsel = (uint32_t)(lane >> 4);
    uint32_t b_chsel = (uint32_t)((lane >> 3) & 1);
    uint32_t lxor    = (uint32_t)(lane & 7);

    float acc[2][8][4];
    #pragma unroll
    for (int mf = 0; mf < 2; mf++)
        #pragma unroll
        for (int nb = 0; nb < 8; nb++)
            #pragma unroll
            for (int i = 0; i < 4; i++) acc[mf][nb][i] = 0.f;

    load_stage(0, 0);
    cp_commit();

    for (int kt = 0; kt < KTT; kt++) {
        cp_wait<0>();
        __syncthreads();
        if (kt + 1 < KTT) {
            load_stage(kt + 1, (kt + 1) & 1);
            cp_commit();
        }

        uint32_t s0 = sb + (kt & 1) * STG2_BYTES;
        #pragma unroll
        for (int ks = 0; ks < 8; ks++) {
            uint32_t ach = (((2 * (uint32_t)ks + a_chsel) ^ lxor) << 4);
            uint32_t bch = (((2 * (uint32_t)ks + b_chsel) ^ lxor) << 4);
            uint32_t af[2][4], bf[4][4];
            #pragma unroll
            for (int mf = 0; mf < 2; mf++)
                ldm4(af[mf][0], af[mf][1], af[mf][2], af[mf][3],
                     s0 + a_rowb[mf] + ach);
            #pragma unroll
            for (int q = 0; q < 4; q++)
                ldm4(bf[q][0], bf[q][1], bf[q][2], bf[q][3],
                     s0 + OFF_B2 + b_rowb[q] + bch);
            #pragma unroll
            for (int q = 0; q < 4; q++) {
                #pragma unroll
                for (int mf = 0; mf < 2; mf++) {
                    mma16816(acc[mf][2*q],   af[mf], bf[q][0], bf[q][1]);
                    mma16816(acc[mf][2*q+1], af[mf], bf[q][2], bf[q][3]);
                }
            }
        }
    }

    const float* bias = b2 + (size_t)e * D_ + n0;
    #pragma unroll
    for (int mf = 0; mf < 2; mf++) {
        #pragma unroll
        for (int hh = 0; hh < 2; hh++) {
            int lr = m_warp + mf * 16 + hh * 8 + (lane >> 2);
            int r  = m0 + lr;
            if (r >= cnt) continue;
            int   tok = g_tok[e * N_ + r];
            float gv  = g_gate[e * N_ + r];
            float* orow = out + (size_t)tok * D_ + n0;
            #pragma unroll
            for (int nb = 0; nb < 8; nb++) {
                int col = n_warp + nb * 8 + 2 * (lane & 3);
                float bx = 0.f, by = 0.f;
                if (split == 0) {
                    float2 bv = *(const float2*)(bias + col);
                    bx = bv.x; by = bv.y;
                }
                atomicAdd(orow + col,     gv * (acc[mf][nb][hh*2]     + bx));
                atomicAdd(orow + col + 1, gv * (acc[mf][nb][hh*2 + 1] + by));
            }
        }
    }
}

// ---------------- launch --------------------------------------------------------
extern "C" void kernel_launch(void* const* d_in, const int* in_sizes, int n_in,
                              void* d_out, int out_size) {
    const float* x  = (const float*)d_in[0];
    const float* gw = (const float*)d_in[1];
    const float* w1 = (const float*)d_in[2];
    const float* b1 = (const float*)d_in[3];
    const float* w2 = (const float*)d_in[4];
    const float* b2 = (const float*)d_in[5];
    float* out = (float*)d_out;

    static void* cnt_ptr = nullptr;
    if (cnt_ptr == nullptr) {
        cudaGetSymbolAddress(&cnt_ptr, g_cnt);
        cudaFuncSetAttribute(gemm1_kernel,
                             cudaFuncAttributeMaxDynamicSharedMemorySize, SMEM1);
        cudaFuncSetAttribute(gemm2_kernel,
                             cudaFuncAttributeMaxDynamicSharedMemorySize, SMEM2);
    }

    cudaMemsetAsync(out, 0, (size_t)out_size * sizeof(float), 0);
    cudaMemsetAsync(cnt_ptr, 0, E_ * sizeof(int), 0);
    gate_kernel<<<N_/8, 256>>>(x, gw);
    prep_w_kernel<<<W1PBLKS + W2PBLKS, 256>>>(w1, w2);

    dim3 g1(F_/BN1, N_/BM1, E_);         // (32, 64, 8), cnt-guarded
    gemm1_kernel<<<g1, NT1, SMEM1>>>(b1);

    dim3 g2(D_/BN2, N_/BM2, E_ * 2);     // (4, 64, 16): split-K=2, cnt-guarded
    gemm2_kernel<<<g2, NT2, SMEM2>>>(b2, out);
}

// round 17
// speedup vs baseline: 1.0358x; 1.0113x over previous
#include <cuda_runtime.h>
#include <cuda_fp16.h>
#include <math.h>
#include <stdint.h>

#define B_ 4
#define T_ 2048
#define D_ 1024
#define E_ 8
#define F_ 4096
#define N_ (B_*T_)            // 8192 tokens

// max M-tiles per expert: cnt_e ~ N(2048, 42^2); 24*128 = 3072 = +24 sigma
#define MAXY 24

// ---- gemm1: CTA 128x128, 8 warps (4m x 2n of 32x64), 2 CTAs/SM ----
#define BM1 128
#define BN1 128
#define BK1 64
#define STAGES1 3
#define NT1 256
#define OFF_B1 16384
#define STG1_BYTES 32768
#define SMEM1 (STAGES1*STG1_BYTES)      // 98304/CTA

// ---- gemm2: CTA 128x256, 16 warps (4m x 4n of 32x64), 1 CTA/SM, split-K=2 ----
#define BM2 128
#define BN2 256
#define BK2 128
#define NT2 512
#define OFF_B2 32768
#define STG2_BYTES 98304
#define SMEM2 (2*STG2_BYTES)            // 196608

// ---------------- device scratch ---------------------------------------------
__device__ int    g_cnt[E_];
__device__ int    g_tok[E_*N_];
__device__ float  g_gate[E_*N_];
__device__ __half g_x_h[(size_t)N_*D_];
__device__ __half g_w1t[(size_t)E_*F_*D_];   // [E][F][D] K-major
__device__ __half g_w2t[(size_t)E_*D_*F_];   // [E][D][F] K-major
__device__ __half g_h[(size_t)N_*2*F_];      // [N*K][F]

// ---------------- helpers -----------------------------------------------------
__device__ __forceinline__ uint32_t smem_u32(const void* p) {
    uint32_t a;
    asm("{ .reg .u64 t; cvta.to.shared.u64 t, %1; cvt.u32.u64 %0, t; }"
        : "=r"(a) : "l"(p));
    return a;
}
__device__ __forceinline__ void cp16(uint32_t dst, const void* src) {
    asm volatile("cp.async.cg.shared.global [%0], [%1], 16;"
                 :: "r"(dst), "l"(src) : "memory");
}
__device__ __forceinline__ void cp_commit() {
    asm volatile("cp.async.commit_group;" ::: "memory");
}
template<int NN>
__device__ __forceinline__ void cp_wait() {
    asm volatile("cp.async.wait_group %0;" :: "n"(NN) : "memory");
}
__device__ __forceinline__ void ldm4(uint32_t& r0, uint32_t& r1,
                                     uint32_t& r2, uint32_t& r3, uint32_t a) {
    asm volatile("ldmatrix.sync.aligned.m8n8.x4.shared.b16 {%0,%1,%2,%3}, [%4];"
                 : "=r"(r0), "=r"(r1), "=r"(r2), "=r"(r3) : "r"(a));
}
__device__ __forceinline__ void mma16816(float* c, const uint32_t* a,
                                         uint32_t b0, uint32_t b1) {
    asm volatile(
        "mma.sync.aligned.m16n8k16.row.col.f32.f16.f16.f32 "
        "{%0,%1,%2,%3}, {%4,%5,%6,%7}, {%8,%9}, {%0,%1,%2,%3};"
        : "+f"(c[0]), "+f"(c[1]), "+f"(c[2]), "+f"(c[3])
        : "r"(a[0]), "r"(a[1]), "r"(a[2]), "r"(a[3]), "r"(b0), "r"(b1));
}
__device__ __forceinline__ uint32_t pack2(__half a, __half b) {
    return (uint32_t)__half_as_ushort(a) | ((uint32_t)__half_as_ushort(b) << 16);
}
__device__ __forceinline__ float gelu_f(float v) {
    return 0.5f * v * (1.f + erff(v * 0.70710678118654752440f));
}

// ------- gate kernel: smem-staged gw + fused x->fp16 conversion ---------------
__global__ void gate_kernel(const float* __restrict__ x,
                            const float* __restrict__ gw) {
    __shared__ float sgw[E_][D_];      // [e][d], 32KB
    int tid = threadIdx.x;
    for (int idx = tid; idx < D_ * E_; idx += 256) {
        int d = idx >> 3, e = idx & 7;
        sgw[e][d] = gw[idx];
    }
    __syncthreads();

    int wid = tid >> 5, lane = tid & 31;
    int t = blockIdx.x * 8 + wid;
    const float* xr = x + (size_t)t * D_;
    uint2* xh = (uint2*)(g_x_h + (size_t)t * D_);
    float acc[E_];
    #pragma unroll
    for (int e = 0; e < E_; e++) acc[e] = 0.f;
    #pragma unroll
    for (int i = 0; i < 8; i++) {
        int d0 = i * 128 + lane * 4;
        float4 v = *(const float4*)(xr + d0);
        xh[d0 >> 2] = make_uint2(
            pack2(__float2half_rn(v.x), __float2half_rn(v.y)),
            pack2(__float2half_rn(v.z), __float2half_rn(v.w)));
        #pragma unroll
        for (int e = 0; e < E_; e++) {
            float4 g = *(const float4*)&sgw[e][d0];   // LDS.128, conflict-free
            acc[e] += v.x * g.x + v.y * g.y + v.z * g.z + v.w * g.w;
        }
    }
    #pragma unroll
    for (int e = 0; e < E_; e++)
        #pragma unroll
        for (int o = 16; o > 0; o >>= 1)
            acc[e] += __shfl_xor_sync(0xffffffffu, acc[e], o);
    if (lane == 0) {
        int i0 = 0; float v0 = acc[0];
        #pragma unroll
        for (int e = 1; e < E_; e++) if (acc[e] > v0) { v0 = acc[e]; i0 = e; }
        int i1 = -1; float v1 = -1e30f;
        #pragma unroll
        for (int e = 0; e < E_; e++) if (e != i0 && acc[e] > v1) { v1 = acc[e]; i1 = e; }
        float e1 = expf(v1 - v0), inv = 1.f / (1.f + e1);
        int p0 = atomicAdd(&g_cnt[i0], 1);
        g_tok[i0 * N_ + p0] = t;  g_gate[i0 * N_ + p0] = inv;
        int p1 = atomicAdd(&g_cnt[i1], 1);
        g_tok[i1 * N_ + p1] = t;  g_gate[i1 * N_ + p1] = e1 * inv;
    }
}

// ------- prep_w: transpose->fp16, 32col x 64row subtile, uint4 stores ---------
#define W1PBLKS ((F_/32)*(D_/64)*E_)            // 16384
#define W2PBLKS ((D_/32)*(F_/64)*E_)            // 16384

__global__ void prep_w_kernel(const float* __restrict__ w1,
                              const float* __restrict__ w2) {
    __shared__ float tile[64][33];
    int bb  = blockIdx.x;
    int tid = threadIdx.x;
    const float* w; __half* wt;
    int RIN, CIN, bid;
    if (bb < W1PBLKS) {
        bid = bb; w = w1; wt = g_w1t; RIN = D_; CIN = F_;
    } else {
        bid = bb - W1PBLKS; w = w2; wt = g_w2t; RIN = F_; CIN = D_;
    }
    int cb = CIN / 32, rb = RIN / 64;
    int e   = bid / (cb * rb);
    int rem = bid % (cb * rb);
    int c0  = (rem % cb) * 32, r0 = (rem / cb) * 64;
    const float* wi = w + (size_t)e * RIN * CIN;
    {   // load: (32, 8) layout, coalesced rows
        int tx = tid & 31, ty = tid >> 5;
        #pragma unroll
        for (int i = 0; i < 8; i++)
            tile[ty + 8*i][tx] = wi[(size_t)(r0 + ty + 8*i) * CIN + c0 + tx];
    }
    __syncthreads();
    // store: thread -> (c = tid>>3, rg = tid&7); pack 8 rows -> one uint4
    {
        int c  = tid >> 3;          // 0..31
        int rg = tid & 7;           // 0..7
        uint32_t p[4];
        #pragma unroll
        for (int k = 0; k < 4; k++)
            p[k] = pack2(__float2half_rn(tile[8*rg + 2*k][c]),
                         __float2half_rn(tile[8*rg + 2*k + 1][c]));
        size_t ob = (size_t)e * CIN * RIN;
        *(uint4*)(wt + ob + (size_t)(c0 + c) * RIN + r0 + 8*rg) =
            make_uint4(p[0], p[1], p[2], p[3]);
    }
}

// ---------------- gemm1: h = gelu(gather(x) @ w1t^T + b1) ---------------------
__global__ __launch_bounds__(NT1, 2)
void gemm1_kernel(const float* __restrict__ b1) {
    int e   = blockIdx.z;
    int cnt = g_cnt[e];
    int m0  = blockIdx.y * BM1;
    if (m0 >= cnt) return;
    int n0  = blockIdx.x * BN1;
    int off = 0;
    #pragma unroll
    for (int j = 0; j < E_; j++) if (j < e) off += g_cnt[j];

    extern __shared__ __align__(1024) char smem[];
    uint32_t sb = smem_u32(smem);
    int tid = threadIdx.x, wid = tid >> 5, lane = tid & 31;

    const __half* Bp = g_w1t + (size_t)e * (size_t)F_ * D_;

    int rbase = tid >> 3;
    int ch    = tid & 7;
    int csw   = ch ^ (rbase & 7);
    uint32_t dst = (uint32_t)(rbase * 128 + csw * 16);

    const __half* a_p[4];
    #pragma unroll
    for (int i = 0; i < 4; i++) {
        int grow = min(m0 + rbase + 32 * i, cnt - 1);
        a_p[i] = g_x_h + (size_t)g_tok[e * N_ + grow] * D_ + ch * 8;
    }
    const __half* b_p = Bp + (size_t)(n0 + rbase) * D_ + ch * 8;

    auto load_stage = [&](int kt, int slot) {
        uint32_t s0 = sb + slot * STG1_BYTES;
        int koff = kt * BK1;
        #pragma unroll
        for (int i = 0; i < 4; i++)
            cp16(s0 + dst + i * 4096u, a_p[i] + koff);
        #pragma unroll
        for (int i = 0; i < 4; i++)
            cp16(s0 + OFF_B1 + dst + i * 4096u, b_p + koff + i * (32 * D_));
    };

    int m_warp = (wid & 3) * 32;
    int n_warp = (wid >> 2) * 64;
    uint32_t a_rowb[2], b_rowb[4];
    #pragma unroll
    for (int mf = 0; mf < 2; mf++)
        a_rowb[mf] = (uint32_t)((m_warp + mf * 16 + (lane & 15)) * 128);
    #pragma unroll
    for (int q = 0; q < 4; q++)
        b_rowb[q] = (uint32_t)((n_warp + q * 16 + ((lane & 16) >> 1) + (lane & 7)) * 128);
    uint32_t a_chsel = (uint32_t)(lane >> 4);
    uint32_t b_chsel = (uint32_t)((lane >> 3) & 1);
    uint32_t lxor    = (uint32_t)(lane & 7);

    float acc[2][8][4];
    #pragma unroll
    for (int mf = 0; mf < 2; mf++)
        #pragma unroll
        for (int nb = 0; nb < 8; nb++)
            #pragma unroll
            for (int i = 0; i < 4; i++) acc[mf][nb][i] = 0.f;

    constexpr int KTT = D_ / BK1;    // 16
    load_stage(0, 0); cp_commit();
    load_stage(1, 1); cp_commit();

    for (int kt = 0; kt < KTT; kt++) {
        cp_wait<1>();
        __syncthreads();

        uint32_t s0 = sb + (kt % STAGES1) * STG1_BYTES;
        #pragma unroll
        for (int ks = 0; ks < 4; ks++) {
            uint32_t ach = (((2 * (uint32_t)ks + a_chsel) ^ lxor) << 4);
            uint32_t bch = (((2 * (uint32_t)ks + b_chsel) ^ lxor) << 4);
            uint32_t af[2][4], bf[4][4];
            #pragma unroll
            for (int mf = 0; mf < 2; mf++)
                ldm4(af[mf][0], af[mf][1], af[mf][2], af[mf][3],
                     s0 + a_rowb[mf] + ach);
            #pragma unroll
            for (int q = 0; q < 4; q++)
                ldm4(bf[q][0], bf[q][1], bf[q][2], bf[q][3],
                     s0 + OFF_B1 + b_rowb[q] + bch);
            #pragma unroll
            for (int q = 0; q < 4; q++) {
                #pragma unroll
                for (int mf = 0; mf < 2; mf++) {
                    mma16816(acc[mf][2*q],   af[mf], bf[q][0], bf[q][1]);
                    mma16816(acc[mf][2*q+1], af[mf], bf[q][2], bf[q][3]);
                }
            }
        }

        if (kt + 2 < KTT) load_stage(kt + 2, (kt + 2) % STAGES1);
        cp_commit();
    }

    const float* bias = b1 + (size_t)e * F_ + n0;
    #pragma unroll
    for (int mf = 0; mf < 2; mf++) {
        #pragma unroll
        for (int hh = 0; hh < 2; hh++) {
            int lr = m_warp + mf * 16 + hh * 8 + (lane >> 2);
            int r  = m0 + lr;
            if (r >= cnt) continue;
            __half* ph = g_h + (size_t)(off + r) * F_ + n0;
            #pragma unroll
            for (int nb = 0; nb < 8; nb++) {
                int col = n_warp + nb * 8 + 2 * (lane & 3);
                float2 bv = *(const float2*)(bias + col);
                float v0 = gelu_f(acc[mf][nb][hh*2]     + bv.x);
                float v1 = gelu_f(acc[mf][nb][hh*2 + 1] + bv.y);
                *(uint32_t*)(ph + col) =
                    pack2(__float2half_rn(v0), __float2half_rn(v1));
            }
        }
    }
}

// ---------------- gemm2: out += gate * (h @ w2t^T + b2), split-K=2 ------------
__global__ __launch_bounds__(NT2, 1)
void gemm2_kernel(const float* __restrict__ b2, float* __restrict__ out) {
    constexpr int KT  = F_;
    constexpr int KTT = (F_/2) / BK2;       // 16

    int z = blockIdx.z;
    int e = z >> 1, split = z & 1;
    int kbase = split * (F_/2);

    int cnt = g_cnt[e];
    int m0  = blockIdx.y * BM2;
    if (m0 >= cnt) return;
    int n0  = blockIdx.x * BN2;
    int off = 0;
    #pragma unroll
    for (int j = 0; j < E_; j++) if (j < e) off += g_cnt[j];

    extern __shared__ __align__(1024) char smem[];
    uint32_t sb = smem_u32(smem);
    int tid = threadIdx.x, wid = tid >> 5, lane = tid & 31;

    const __half* Bp = g_w2t + (size_t)e * (size_t)D_ * KT;

    int rbase = tid >> 4;              // 0..31
    int ch    = tid & 15;
    int csw   = ch ^ (rbase & 7);
    uint32_t dst = (uint32_t)(rbase * 256 + csw * 16);

    const __half* a_p[4];
    #pragma unroll
    for (int i = 0; i < 4; i++) {
        int grow = min(m0 + rbase + 32 * i, cnt - 1);
        a_p[i] = g_h + (size_t)(off + grow) * KT + ch * 8 + kbase;
    }
    const __half* b_p = Bp + (size_t)(n0 + rbase) * KT + ch * 8 + kbase;

    auto load_stage = [&](int kt, int slot) {
        uint32_t s0 = sb + slot * STG2_BYTES;
        int koff = kt * BK2;
        #pragma unroll
        for (int i = 0; i < 4; i++)
            cp16(s0 + dst + i * 8192u, a_p[i] + koff);
        #pragma unroll
        for (int i = 0; i < 8; i++)
            cp16(s0 + OFF_B2 + dst + i * 8192u, b_p + koff + i * (32 * KT));
    };

    int m_warp = (wid & 3) * 32;
    int n_warp = (wid >> 2) * 64;
    uint32_t a_rowb[2], b_rowb[4];
    #pragma unroll
    for (int mf = 0; mf < 2; mf++)
        a_rowb[mf] = (uint32_t)((m_warp + mf * 16 + (lane & 15)) * 256);
    #pragma unroll
    for (int q = 0; q < 4; q++)
        b_rowb[q] = (uint32_t)((n_warp + q * 16 + ((lane & 16) >> 1) + (lane & 7)) * 256);
    uint32_t a_chsel = (uint32_t)(lane >> 4);
    uint32_t b_chsel = (uint32_t)((lane >> 3) & 1);
    uint32_t lxor    = (uint32_t)(lane & 7);

    float acc[2][8][4];
    #pragma unroll
    for (int mf = 0; mf < 2; mf++)
        #pragma unroll
        for (int nb = 0; nb < 8; nb++)
            #pragma unroll
            for (int i = 0; i < 4; i++) acc[mf][nb][i] = 0.f;

    load_stage(0, 0);
    cp_commit();

    for (int kt = 0; kt < KTT; kt++) {
        cp_wait<0>();
        __syncthreads();
        if (kt + 1 < KTT) {
            load_stage(kt + 1, (kt + 1) & 1);
            cp_commit();
        }

        uint32_t s0 = sb + (kt & 1) * STG2_BYTES;
        #pragma unroll
        for (int ks = 0; ks < 8; ks++) {
            uint32_t ach = (((2 * (uint32_t)ks + a_chsel) ^ lxor) << 4);
            uint32_t bch = (((2 * (uint32_t)ks + b_chsel) ^ lxor) << 4);
            uint32_t af[2][4], bf[4][4];
            #pragma unroll
            for (int mf = 0; mf < 2; mf++)
                ldm4(af[mf][0], af[mf][1], af[mf][2], af[mf][3],
                     s0 + a_rowb[mf] + ach);
            #pragma unroll
            for (int q = 0; q < 4; q++)
                ldm4(bf[q][0], bf[q][1], bf[q][2], bf[q][3],
                     s0 + OFF_B2 + b_rowb[q] + bch);
            #pragma unroll
            for (int q = 0; q < 4; q++) {
                #pragma unroll
                for (int mf = 0; mf < 2; mf++) {
                    mma16816(acc[mf][2*q],   af[mf], bf[q][0], bf[q][1]);
                    mma16816(acc[mf][2*q+1], af[mf], bf[q][2], bf[q][3]);
                }
            }
        }
    }

    const float* bias = b2 + (size_t)e * D_ + n0;
    #pragma unroll
    for (int mf = 0; mf < 2; mf++) {
        #pragma unroll
        for (int hh = 0; hh < 2; hh++) {
            int lr = m_warp + mf * 16 + hh * 8 + (lane >> 2);
            int r  = m0 + lr;
            if (r >= cnt) continue;
            int   tok = g_tok[e * N_ + r];
            float gv  = g_gate[e * N_ + r];
            float* orow = out + (size_t)tok * D_ + n0;
            #pragma unroll
            for (int nb = 0; nb < 8; nb++) {
                int col = n_warp + nb * 8 + 2 * (lane & 3);
                float bx = 0.f, by = 0.f;
                if (split == 0) {
                    float2 bv = *(const float2*)(bias + col);
                    bx = bv.x; by = bv.y;
                }
                atomicAdd(orow + col,     gv * (acc[mf][nb][hh*2]     + bx));
                atomicAdd(orow + col + 1, gv * (acc[mf][nb][hh*2 + 1] + by));
            }
        }
    }
}

// ---------------- launch --------------------------------------------------------
extern "C" void kernel_launch(void* const* d_in, const int* in_sizes, int n_in,
                              void* d_out, int out_size) {
    const float* x  = (const float*)d_in[0];
    const float* gw = (const float*)d_in[1];
    const float* w1 = (const float*)d_in[2];
    const float* b1 = (const float*)d_in[3];
    const float* w2 = (const float*)d_in[4];
    const float* b2 = (const float*)d_in[5];
    float* out = (float*)d_out;

    static void* cnt_ptr = nullptr;
    if (cnt_ptr == nullptr) {
        cudaGetSymbolAddress(&cnt_ptr, g_cnt);
        cudaFuncSetAttribute(gemm1_kernel,
                             cudaFuncAttributeMaxDynamicSharedMemorySize, SMEM1);
        cudaFuncSetAttribute(gemm2_kernel,
                             cudaFuncAttributeMaxDynamicSharedMemorySize, SMEM2);
    }

    cudaMemsetAsync(out, 0, (size_t)out_size * sizeof(float), 0);
    cudaMemsetAsync(cnt_ptr, 0, E_ * sizeof(int), 0);
    gate_kernel<<<N_/8, 256>>>(x, gw);
    prep_w_kernel<<<W1PBLKS + W2PBLKS, 256>>>(w1, w2);

    dim3 g1(F_/BN1, MAXY, E_);         // (32, 24, 8): cnt <= 3072 guaranteed
    gemm1_kernel<<<g1, NT1, SMEM1>>>(b1);

    dim3 g2(D_/BN2, MAXY, E_ * 2);     // (4, 24, 16): split-K=2
    gemm2_kernel<<<g2, NT2, SMEM2>>>(b2, out);
}